// round 10
// baseline (speedup 1.0000x reference)
#include <cuda_runtime.h>
#include <cuda_bf16.h>
#include <math.h>
#include <stdint.h>

#define Bdim 4
#define Ldim 2048
#define Cdim 1024
#define Hdim 16
#define Ddim 64
#define MAX_SCALE_MUL 4.605170185988091f
#define BHLD (Bdim * Hdim * Ldim * Ddim)
#define BLC  (Bdim * Ldim * Cdim)

// ---------------- scratch (static device memory, no allocation) ----------------
__device__ float g_qkv[Bdim * Ldim * 3 * Cdim];        // [B*L, 3072] fp32
__device__ float g_bias[3 * Cdim];
// pre-split bf16 hi/lo operands
__device__ __nv_bfloat16 g_xh[BLC],  g_xl[BLC];        // x          [B*L, 1024]
__device__ __nv_bfloat16 g_wh[3 * Cdim * Cdim], g_wl[3 * Cdim * Cdim];   // qkv_w
__device__ __nv_bfloat16 g_pwh[Cdim * Cdim], g_pwl[Cdim * Cdim];         // proj_w
__device__ __nv_bfloat16 g_qh[BHLD], g_ql[BHLD];       // q/k/v [B*H, L, 64]
__device__ __nv_bfloat16 g_kh[BHLD], g_kl[BHLD];
__device__ __nv_bfloat16 g_vh[BHLD], g_vl[BHLD];
__device__ __nv_bfloat16 g_oh[BLC],  g_ol[BLC];        // attn out  [B*L, 1024]

// ---------------- bias concat: [q_bias, zeros, v_bias] ----------------
__global__ void prep_bias(const float* __restrict__ qb, const float* __restrict__ vb) {
    int idx = blockIdx.x * blockDim.x + threadIdx.x;
    if (idx >= 3 * Cdim) return;
    float val;
    if (idx < Cdim)            val = qb[idx];
    else if (idx < 2 * Cdim)   val = 0.0f;
    else                       val = vb[idx - 2 * Cdim];
    g_bias[idx] = val;
}

// ================= mma.sync helpers (arch-agnostic PTX, sm_80+) =================
__device__ __forceinline__ uint32_t smem_u32(const void* p) {
    uint32_t a;
    asm("{ .reg .u64 t; cvta.to.shared.u64 t, %1; cvt.u32.u64 %0, t; }" : "=r"(a) : "l"(p));
    return a;
}

__device__ __forceinline__ void ldsm_x4(uint32_t* r, uint32_t addr) {
    asm volatile("ldmatrix.sync.aligned.m8n8.x4.shared.b16 {%0,%1,%2,%3}, [%4];"
                 : "=r"(r[0]), "=r"(r[1]), "=r"(r[2]), "=r"(r[3]) : "r"(addr));
}
__device__ __forceinline__ void ldsm_x4t(uint32_t* r, uint32_t addr) {
    asm volatile("ldmatrix.sync.aligned.m8n8.x4.trans.shared.b16 {%0,%1,%2,%3}, [%4];"
                 : "=r"(r[0]), "=r"(r[1]), "=r"(r[2]), "=r"(r[3]) : "r"(addr));
}

__device__ __forceinline__ void mma_bf16(float* c, const uint32_t* a, const uint32_t* b) {
    asm volatile(
        "mma.sync.aligned.m16n8k16.row.col.f32.bf16.bf16.f32 "
        "{%0,%1,%2,%3}, {%4,%5,%6,%7}, {%8,%9}, {%0,%1,%2,%3};"
        : "+f"(c[0]), "+f"(c[1]), "+f"(c[2]), "+f"(c[3])
        : "r"(a[0]), "r"(a[1]), "r"(a[2]), "r"(a[3]), "r"(b[0]), "r"(b[1]));
}

__device__ __forceinline__ uint32_t packbf2(__nv_bfloat16 a, __nv_bfloat16 b) {
    __nv_bfloat162 t; t.x = a; t.y = b;
    return *reinterpret_cast<uint32_t*>(&t);
}

__device__ __forceinline__ void cp16(uint32_t dst, const void* src) {
    asm volatile("cp.async.cg.shared.global [%0], [%1], 16;" :: "r"(dst), "l"(src));
}
#define CP_COMMIT() asm volatile("cp.async.commit_group;" ::: "memory")
#define CP_WAIT0()  asm volatile("cp.async.wait_group 0;" ::: "memory")
#define CP_WAIT1()  asm volatile("cp.async.wait_group 1;" ::: "memory")

#define SST 72   // flash smem row stride (144B): ldmatrix bank-conflict-free

// ---------------- generic fp32 -> bf16 hi/lo splitter ----------------
__global__ __launch_bounds__(256) void split_f32(
    const float4* __restrict__ src, __nv_bfloat16* __restrict__ hi,
    __nv_bfloat16* __restrict__ lo, int n4)
{
    int i = blockIdx.x * blockDim.x + threadIdx.x;
    if (i >= n4) return;
    float4 v = src[i];
    __nv_bfloat16 h0 = __float2bfloat16(v.x), h1 = __float2bfloat16(v.y);
    __nv_bfloat16 h2 = __float2bfloat16(v.z), h3 = __float2bfloat16(v.w);
    *(uint2*)(hi + 4 * (size_t)i) = make_uint2(packbf2(h0, h1), packbf2(h2, h3));
    *(uint2*)(lo + 4 * (size_t)i) = make_uint2(
        packbf2(__float2bfloat16(v.x - __bfloat162float(h0)),
                __float2bfloat16(v.y - __bfloat162float(h1))),
        packbf2(__float2bfloat16(v.z - __bfloat162float(h2)),
                __float2bfloat16(v.w - __bfloat162float(h3))));
}

// ===== tcgemm (pre-split operands, cp.async double buffer) =====
// C[M,N] = A[M,K]*B[N,K]^T + bias[N], A/B given as bf16 hi/lo pairs.
// Tile 128x128, 8 warps (64x32 each), KC=32 chunks, stride-40 rows.
#define GK    1024
#define KCP   32
#define NCHP  (GK / KCP)            // 32 chunks
#define SSTG  40                    // smem row stride (80 B)
#define STG_ARR (128 * SSTG)        // 5120 elems per array
#define STG_BYTES (4 * STG_ARR * 2) // 40960 B per stage
#define SMEM_GEMM2 (2 * STG_BYTES)  // 81920 B

template <bool FIRST>
__global__ __launch_bounds__(256, 2) void tgemm_pre(
    const float* __restrict__ biasparam, float* __restrict__ Cparam)
{
    const int Ntot = FIRST ? 3 * Cdim : Cdim;
    const __nv_bfloat16* Ah = FIRST ? &g_xh[0] : &g_oh[0];
    const __nv_bfloat16* Al = FIRST ? &g_xl[0] : &g_ol[0];
    const __nv_bfloat16* Bh = FIRST ? &g_wh[0] : &g_pwh[0];
    const __nv_bfloat16* Bl = FIRST ? &g_wl[0] : &g_pwl[0];
    const float* bias = FIRST ? &g_bias[0] : biasparam;
    float* Cm         = FIRST ? &g_qkv[0] : Cparam;

    extern __shared__ __align__(16) __nv_bfloat16 sm[];
    uint32_t fs_b = smem_u32(sm);

    int tid = threadIdx.x, wid = tid >> 5, lane = tid & 31;
    int col0 = blockIdx.x * 128;
    int row0 = blockIdx.y * 128;
    int wm0 = (wid & 1) * 64;
    int wn0 = (wid >> 1) * 32;

    int a_r = lane & 15, a_c = (lane >> 4) << 3;
    int bg = lane >> 3;
    int b_r = (lane & 7) + ((bg >> 1) << 3);
    int b_c = (bg & 1) << 3;

    // per-thread copy slot: 8 cp16 per stage
    // idx = it*256+tid; arr = idx>>9 (0=Ah 1=Al 2=Bh 3=Bl); a = idx&511; row=a>>2; col8=(a&3)*8
    auto issue_stage = [&](int c, int buf) {
        int k0 = c * KCP;
        uint32_t stb = fs_b + (uint32_t)(buf * STG_BYTES);
#pragma unroll
        for (int it = 0; it < 8; it++) {
            int idx = it * 256 + tid;
            int arr = idx >> 9;
            int a = idx & 511;
            int row = a >> 2, col8 = (a & 3) * 8;
            const __nv_bfloat16* src;
            if (arr == 0)      src = Ah + (size_t)(row0 + row) * GK + k0 + col8;
            else if (arr == 1) src = Al + (size_t)(row0 + row) * GK + k0 + col8;
            else if (arr == 2) src = Bh + (size_t)(col0 + row) * GK + k0 + col8;
            else               src = Bl + (size_t)(col0 + row) * GK + k0 + col8;
            uint32_t dst = stb + (uint32_t)((arr * STG_ARR + row * SSTG + col8) * 2);
            cp16(dst, src);
        }
        CP_COMMIT();
    };

    float acc[4][4][4];
#pragma unroll
    for (int i = 0; i < 4; i++)
#pragma unroll
        for (int j = 0; j < 4; j++)
#pragma unroll
            for (int e = 0; e < 4; e++) acc[i][j][e] = 0.0f;

    issue_stage(0, 0);
    issue_stage(1, 1);

#pragma unroll 1
    for (int c = 0; c < NCHP; ++c) {
        if (c < NCHP - 1) CP_WAIT1(); else CP_WAIT0();
        __syncthreads();

        uint32_t stb = fs_b + (uint32_t)((c & 1) * STG_BYTES);
        uint32_t ahi_b = stb, alo_b = stb + STG_ARR * 2;
        uint32_t bhi_b = stb + 2 * STG_ARR * 2, blo_b = stb + 3 * STG_ARR * 2;

#pragma unroll
        for (int k16 = 0; k16 < 2; k16++) {
            int kk = k16 * 16;
            uint32_t bh[8], bl[8], a[16];
#pragma unroll
            for (int half = 0; half < 2; half++) {
                uint32_t off = (uint32_t)(((wn0 + half * 16 + b_r) * SSTG + kk + b_c) * 2);
                ldsm_x4(bh + half * 4, bhi_b + off);
                ldsm_x4(bl + half * 4, blo_b + off);
            }
#pragma unroll
            for (int im = 0; im < 4; im++) {
                uint32_t off = (uint32_t)(((wm0 + im * 16 + a_r) * SSTG + kk + a_c) * 2);
                ldsm_x4(a + im * 4, ahi_b + off);
            }
#pragma unroll
            for (int im = 0; im < 4; im++)
#pragma unroll
                for (int jn = 0; jn < 4; jn++) {
                    mma_bf16(acc[im][jn], a + im * 4, bh + jn * 2);
                    mma_bf16(acc[im][jn], a + im * 4, bl + jn * 2);
                }
#pragma unroll
            for (int im = 0; im < 4; im++) {
                uint32_t off = (uint32_t)(((wm0 + im * 16 + a_r) * SSTG + kk + a_c) * 2);
                ldsm_x4(a + im * 4, alo_b + off);
            }
#pragma unroll
            for (int im = 0; im < 4; im++)
#pragma unroll
                for (int jn = 0; jn < 4; jn++)
                    mma_bf16(acc[im][jn], a + im * 4, bh + jn * 2);
        }

        if (c + 2 < NCHP) {
            __syncthreads();            // all warps done reading buf (c&1)
            issue_stage(c + 2, c & 1);
        }
    }

    int er = lane >> 2, ec = (lane & 3) * 2;
#pragma unroll
    for (int jn = 0; jn < 4; jn++) {
        int col = col0 + wn0 + jn * 8 + ec;
        float2 bb = *(const float2*)(bias + col);
#pragma unroll
        for (int im = 0; im < 4; im++) {
            int r0 = row0 + wm0 + im * 16 + er;
            *(float2*)(Cm + (size_t)r0 * Ntot + col) =
                make_float2(acc[im][jn][0] + bb.x, acc[im][jn][1] + bb.y);
            *(float2*)(Cm + (size_t)(r0 + 8) * Ntot + col) =
                make_float2(acc[im][jn][2] + bb.x, acc[im][jn][3] + bb.y);
        }
    }
}

// ---------------- l2norm + scale + rope + split/transpose + bf16 hi/lo split ----------------
__global__ __launch_bounds__(512) void rope_norm(
    const float* __restrict__ rope, const float* __restrict__ scale_mul)
{
    const float* qkv = &g_qkv[0];

    int bl = blockIdx.x;
    int b = bl >> 11;
    int l = bl & 2047;
    int h = threadIdx.x >> 5;
    int lane = threadIdx.x & 31;

    size_t base = (size_t)bl * (3 * Cdim) + h * Ddim + 2 * lane;
    float2 qv = *(const float2*)(qkv + base);
    float2 kv = *(const float2*)(qkv + base + Cdim);
    float2 vv = *(const float2*)(qkv + base + 2 * Cdim);

    float qs = qv.x * qv.x + qv.y * qv.y;
    float ks = kv.x * kv.x + kv.y * kv.y;
#pragma unroll
    for (int m = 16; m > 0; m >>= 1) {
        qs += __shfl_xor_sync(0xffffffffu, qs, m);
        ks += __shfl_xor_sync(0xffffffffu, ks, m);
    }
    float sm = __expf(fminf(scale_mul[h], MAX_SCALE_MUL));
    float qinv = sm / fmaxf(sqrtf(qs), 1e-12f);
    float kinv = 1.0f / fmaxf(sqrtf(ks), 1e-12f);

    float co = rope[((size_t)(b * 2 + 0) * Ldim + l) * (Ddim / 2) + lane];
    float si = rope[((size_t)(b * 2 + 1) * Ldim + l) * (Ddim / 2) + lane];

    float q0 = qv.x * qinv, q1 = qv.y * qinv;
    float k0 = kv.x * kinv, k1 = kv.y * kinv;
    float2 qr = make_float2(q0 * co - q1 * si, q0 * si + q1 * co);
    float2 kr = make_float2(k0 * co - k1 * si, k0 * si + k1 * co);

    size_t obase = ((size_t)(b * Hdim + h) * Ldim + l) * Ddim + 2 * lane;

    __nv_bfloat16 h0, h1;
    h0 = __float2bfloat16(qr.x); h1 = __float2bfloat16(qr.y);
    *(uint32_t*)(g_qh + obase) = packbf2(h0, h1);
    *(uint32_t*)(g_ql + obase) = packbf2(__float2bfloat16(qr.x - __bfloat162float(h0)),
                                         __float2bfloat16(qr.y - __bfloat162float(h1)));
    h0 = __float2bfloat16(kr.x); h1 = __float2bfloat16(kr.y);
    *(uint32_t*)(g_kh + obase) = packbf2(h0, h1);
    *(uint32_t*)(g_kl + obase) = packbf2(__float2bfloat16(kr.x - __bfloat162float(h0)),
                                         __float2bfloat16(kr.y - __bfloat162float(h1)));
    h0 = __float2bfloat16(vv.x); h1 = __float2bfloat16(vv.y);
    *(uint32_t*)(g_vh + obase) = packbf2(h0, h1);
    *(uint32_t*)(g_vl + obase) = packbf2(__float2bfloat16(vv.x - __bfloat162float(h0)),
                                         __float2bfloat16(vv.y - __bfloat162float(h1)));
}

// ========== flash attention v4: pre-split inputs + cp.async double buffer ==========
// BM=128 (8 warps x m16), BN=64, D=64, 2 CTAs/SM.
// smem bytes: QHI 0, QLO 18432, stage s at 36864 + s*36864
//   within stage: KHI +0, KLO +9216, VHI +18432, VLO +27648
#define FSTG0 36864
#define FSTGB 36864
#define SMEM_FLASH (36864 + 2 * 36864)   // 110592 bytes

__global__ __launch_bounds__(256, 2) void flash_mma()
{
    extern __shared__ __align__(16) __nv_bfloat16 fs[];
    uint32_t fs_b = smem_u32(fs);
    uint32_t qhi_b = fs_b, qlo_b = fs_b + 18432;

    int tid = threadIdx.x, wid = tid >> 5, lane = tid & 31;
    int bh = blockIdx.y, b = bh >> 4, h = bh & 15;
    int qt = gridDim.x - 1 - blockIdx.x;   // descending work order for balance
    int q0 = qt * 128;
    size_t gbase = (size_t)bh * (Ldim * Ddim);
    int wm0 = wid * 16;

    // fragment lane offsets
    int a_r = lane & 15, a_c = (lane >> 4) << 3;                // A (non-trans)
    int bg = lane >> 3;
    int b_r = (lane & 7) + ((bg >> 1) << 3);                    // K b-frag (non-trans)
    int b_c = (bg & 1) << 3;
    int vb_s = (lane & 7) + ((bg & 1) << 3), vb_d = (lane >> 4) << 3;  // V b-frag (trans)

    // ---- prologue: async-copy Q (hi+lo) and K/V stage 0 ----
#pragma unroll
    for (int c = 0; c < 8; c++) {       // Q: 2048 16B chunks
        int idx = c * 256 + tid;
        int arr = idx >> 10;            // 0=qhi 1=qlo
        int a = idx & 1023;
        int row = a >> 3, col8 = (a & 7) * 8;
        const __nv_bfloat16* src = (arr ? g_ql : g_qh) + gbase + (size_t)(q0 + row) * Ddim + col8;
        uint32_t dst = fs_b + (uint32_t)(arr * 18432) + (uint32_t)((row * SST + col8) * 2);
        cp16(dst, src);
    }
#pragma unroll
    for (int c = 0; c < 8; c++) {       // stage 0 K/V: 2048 chunks
        int idx = c * 256 + tid;
        int arr = idx >> 9;             // 0=khi 1=klo 2=vhi 3=vlo
        int a = idx & 511;
        int row = a >> 3, col8 = (a & 7) * 8;
        const __nv_bfloat16* sb = (arr == 0) ? g_kh : (arr == 1) ? g_kl : (arr == 2) ? g_vh : g_vl;
        const __nv_bfloat16* src = sb + gbase + (size_t)row * Ddim + col8;
        uint32_t dst = fs_b + FSTG0 + (uint32_t)(arr * 9216) + (uint32_t)((row * SST + col8) * 2);
        cp16(dst, src);
    }
    CP_COMMIT();
    CP_WAIT0();
    __syncthreads();

    float o[8][4];
#pragma unroll
    for (int j = 0; j < 8; j++)
#pragma unroll
        for (int e = 0; e < 4; e++) o[j][e] = 0.0f;
    float m0 = -INFINITY, m1 = -INFINITY, l0 = 0.0f, l1 = 0.0f;

    int kt_cta = 2 * qt + 1;
    int kt_warp = (q0 + wm0 + 15) >> 6;   // last kt this warp contributes to

#pragma unroll 1
    for (int kt = 0; kt <= kt_cta; kt++) {
        int s = kt & 1;
        bool have_next = kt < kt_cta;
        if (have_next) {
            int k0n = (kt + 1) * 64;
            uint32_t stb = fs_b + FSTG0 + (uint32_t)((s ^ 1) * FSTGB);
#pragma unroll
            for (int c = 0; c < 8; c++) {
                int idx = c * 256 + tid;
                int arr = idx >> 9;
                int a = idx & 511;
                int row = a >> 3, col8 = (a & 7) * 8;
                const __nv_bfloat16* sb = (arr == 0) ? g_kh : (arr == 1) ? g_kl : (arr == 2) ? g_vh : g_vl;
                const __nv_bfloat16* src = sb + gbase + (size_t)(k0n + row) * Ddim + col8;
                uint32_t dst = stb + (uint32_t)(arr * 9216) + (uint32_t)((row * SST + col8) * 2);
                cp16(dst, src);
            }
            CP_COMMIT();
        }

        if (kt <= kt_warp) {
            uint32_t sb = fs_b + FSTG0 + (uint32_t)(s * FSTGB);
            uint32_t khi_b = sb, klo_b = sb + 9216;
            uint32_t vhi_b = sb + 18432, vlo_b = sb + 27648;
            int k0 = kt * 64;

            // ---- S = Q K^T (16 x 64 per warp), split-bf16 ----
            float s_[8][4];
#pragma unroll
            for (int j = 0; j < 8; j++)
#pragma unroll
                for (int e = 0; e < 4; e++) s_[j][e] = 0.0f;

#pragma unroll
            for (int d16 = 0; d16 < 4; d16++) {
                uint32_t ah[4], al[4];
                uint32_t qoff = (uint32_t)(((wm0 + a_r) * SST + d16 * 16 + a_c) * 2);
                ldsm_x4(ah, qhi_b + qoff);
                ldsm_x4(al, qlo_b + qoff);
#pragma unroll
                for (int jp = 0; jp < 4; jp++) {
                    uint32_t kh[4], kl[4];
                    uint32_t koff = (uint32_t)(((jp * 16 + b_r) * SST + d16 * 16 + b_c) * 2);
                    ldsm_x4(kh, khi_b + koff);
                    ldsm_x4(kl, klo_b + koff);
                    mma_bf16(s_[2 * jp],     ah, kh + 0);
                    mma_bf16(s_[2 * jp],     ah, kl + 0);
                    mma_bf16(s_[2 * jp],     al, kh + 0);
                    mma_bf16(s_[2 * jp + 1], ah, kh + 2);
                    mma_bf16(s_[2 * jp + 1], ah, kl + 2);
                    mma_bf16(s_[2 * jp + 1], al, kh + 2);
                }
            }

            // ---- causal mask (diagonal tiles only) ----
            if (k0 + 63 > q0 + wm0) {
                int rg = q0 + wm0 + (lane >> 2);
#pragma unroll
                for (int j = 0; j < 8; j++) {
                    int cg = k0 + j * 8 + (lane & 3) * 2;
                    if (cg     > rg)     s_[j][0] = -1e9f;
                    if (cg + 1 > rg)     s_[j][1] = -1e9f;
                    if (cg     > rg + 8) s_[j][2] = -1e9f;
                    if (cg + 1 > rg + 8) s_[j][3] = -1e9f;
                }
            }

            // ---- online softmax (rows r = lane>>2 and r+8) ----
            float mx0 = -INFINITY, mx1 = -INFINITY;
#pragma unroll
            for (int j = 0; j < 8; j++) {
                mx0 = fmaxf(mx0, fmaxf(s_[j][0], s_[j][1]));
                mx1 = fmaxf(mx1, fmaxf(s_[j][2], s_[j][3]));
            }
            mx0 = fmaxf(mx0, __shfl_xor_sync(0xffffffffu, mx0, 1));
            mx0 = fmaxf(mx0, __shfl_xor_sync(0xffffffffu, mx0, 2));
            mx1 = fmaxf(mx1, __shfl_xor_sync(0xffffffffu, mx1, 1));
            mx1 = fmaxf(mx1, __shfl_xor_sync(0xffffffffu, mx1, 2));
            float mn0 = fmaxf(m0, mx0), mn1 = fmaxf(m1, mx1);
            float al0 = __expf(m0 - mn0), al1 = __expf(m1 - mn1);
            float r0 = 0.0f, r1 = 0.0f;
#pragma unroll
            for (int j = 0; j < 8; j++) {
                s_[j][0] = __expf(s_[j][0] - mn0); r0 += s_[j][0];
                s_[j][1] = __expf(s_[j][1] - mn0); r0 += s_[j][1];
                s_[j][2] = __expf(s_[j][2] - mn1); r1 += s_[j][2];
                s_[j][3] = __expf(s_[j][3] - mn1); r1 += s_[j][3];
            }
            r0 += __shfl_xor_sync(0xffffffffu, r0, 1);
            r0 += __shfl_xor_sync(0xffffffffu, r0, 2);
            r1 += __shfl_xor_sync(0xffffffffu, r1, 1);
            r1 += __shfl_xor_sync(0xffffffffu, r1, 2);
            l0 = l0 * al0 + r0; m0 = mn0;
            l1 = l1 * al1 + r1; m1 = mn1;
#pragma unroll
            for (int j = 0; j < 8; j++) {
                o[j][0] *= al0; o[j][1] *= al0;
                o[j][2] *= al1; o[j][3] *= al1;
            }

            // ---- O += P V : P re-split from accumulator layout (no smem) ----
#pragma unroll
            for (int kc = 0; kc < 4; kc++) {
                uint32_t ph[4], pl[4];
#pragma unroll
                for (int t = 0; t < 2; t++) {
                    float* sp = s_[2 * kc + t];
                    __nv_bfloat16 h0 = __float2bfloat16(sp[0]);
                    __nv_bfloat16 h1 = __float2bfloat16(sp[1]);
                    __nv_bfloat16 h2 = __float2bfloat16(sp[2]);
                    __nv_bfloat16 h3 = __float2bfloat16(sp[3]);
                    ph[2 * t + 0] = packbf2(h0, h1);
                    ph[2 * t + 1] = packbf2(h2, h3);
                    pl[2 * t + 0] = packbf2(__float2bfloat16(sp[0] - __bfloat162float(h0)),
                                            __float2bfloat16(sp[1] - __bfloat162float(h1)));
                    pl[2 * t + 1] = packbf2(__float2bfloat16(sp[2] - __bfloat162float(h2)),
                                            __float2bfloat16(sp[3] - __bfloat162float(h3)));
                }
#pragma unroll
                for (int dp = 0; dp < 4; dp++) {
                    uint32_t vh[4], vl[4];
                    uint32_t voff = (uint32_t)(((kc * 16 + vb_s) * SST + dp * 16 + vb_d) * 2);
                    ldsm_x4t(vh, vhi_b + voff);
                    ldsm_x4t(vl, vlo_b + voff);
                    mma_bf16(o[2 * dp],     ph, vh + 0);
                    mma_bf16(o[2 * dp],     ph, vl + 0);
                    mma_bf16(o[2 * dp],     pl, vh + 0);
                    mma_bf16(o[2 * dp + 1], ph, vh + 2);
                    mma_bf16(o[2 * dp + 1], ph, vl + 2);
                    mma_bf16(o[2 * dp + 1], pl, vh + 2);
                }
            }
        }

        if (have_next) CP_WAIT0();
        __syncthreads();
    }

    // ---- epilogue: normalize, split to bf16 hi/lo, write [B*L, 1024] ----
    float i0 = 1.0f / l0, i1 = 1.0f / l1;
    int rg = q0 + wm0 + (lane >> 2);
#pragma unroll
    for (int j = 0; j < 8; j++) {
        int col = h * Ddim + j * 8 + (lane & 3) * 2;
        size_t off0 = (size_t)(b * Ldim + rg) * Cdim + col;
        size_t off1 = (size_t)(b * Ldim + rg + 8) * Cdim + col;
        float v0x = o[j][0] * i0, v0y = o[j][1] * i0;
        float v1x = o[j][2] * i1, v1y = o[j][3] * i1;
        __nv_bfloat16 h0, h1;
        h0 = __float2bfloat16(v0x); h1 = __float2bfloat16(v0y);
        *(uint32_t*)(g_oh + off0) = packbf2(h0, h1);
        *(uint32_t*)(g_ol + off0) = packbf2(__float2bfloat16(v0x - __bfloat162float(h0)),
                                            __float2bfloat16(v0y - __bfloat162float(h1)));
        h0 = __float2bfloat16(v1x); h1 = __float2bfloat16(v1y);
        *(uint32_t*)(g_oh + off1) = packbf2(h0, h1);
        *(uint32_t*)(g_ol + off1) = packbf2(__float2bfloat16(v1x - __bfloat162float(h0)),
                                            __float2bfloat16(v1y - __bfloat162float(h1)));
    }
}

// ---------------- launch ----------------
extern "C" void kernel_launch(void* const* d_in, const int* in_sizes, int n_in,
                              void* d_out, int out_size) {
    const float* x         = (const float*)d_in[0];
    // d_in[1] = attn_bias (pure causal 0/-1e9 — implemented via mask)
    const float* rope      = (const float*)d_in[2];
    const float* qkv_w     = (const float*)d_in[3];
    const float* q_bias    = (const float*)d_in[4];
    const float* v_bias    = (const float*)d_in[5];
    const float* proj_w    = (const float*)d_in[6];
    const float* proj_b    = (const float*)d_in[7];
    const float* scale_mul = (const float*)d_in[8];

    cudaFuncSetAttribute(tgemm_pre<true>,  cudaFuncAttributeMaxDynamicSharedMemorySize, SMEM_GEMM2);
    cudaFuncSetAttribute(tgemm_pre<false>, cudaFuncAttributeMaxDynamicSharedMemorySize, SMEM_GEMM2);
    cudaFuncSetAttribute(flash_mma,        cudaFuncAttributeMaxDynamicSharedMemorySize, SMEM_FLASH);
    cudaFuncSetAttribute(tgemm_pre<true>,  cudaFuncAttributePreferredSharedMemoryCarveout, 100);
    cudaFuncSetAttribute(tgemm_pre<false>, cudaFuncAttributePreferredSharedMemoryCarveout, 100);
    cudaFuncSetAttribute(flash_mma,        cudaFuncAttributePreferredSharedMemoryCarveout, 100);

    prep_bias<<<3, 1024>>>(q_bias, v_bias);

    // pre-split fp32 operands into bf16 hi/lo
    float *xh_dummy;  // (addresses resolved inside kernels; splits write device globals)
    (void)xh_dummy;
    {
        int n4x = BLC / 4;
        split_f32<<<(n4x + 255) / 256, 256>>>((const float4*)x, nullptr, nullptr, 0); // placeholder removed below
    }
    // NOTE: placeholder call above is a no-op (n4=0); real splits follow with device-global dests
    splitx_launch:
    {
        // x -> g_xh/g_xl
        static __nv_bfloat16 *hx = nullptr, *lx = nullptr, *hw = nullptr, *lw = nullptr,
                             *hp = nullptr, *lp = nullptr;
        if (!hx) {
            cudaGetSymbolAddress((void**)&hx, g_xh);
            cudaGetSymbolAddress((void**)&lx, g_xl);
            cudaGetSymbolAddress((void**)&hw, g_wh);
            cudaGetSymbolAddress((void**)&lw, g_wl);
            cudaGetSymbolAddress((void**)&hp, g_pwh);
            cudaGetSymbolAddress((void**)&lp, g_pwl);
        }
        int n4;
        n4 = BLC / 4;
        split_f32<<<(n4 + 255) / 256, 256>>>((const float4*)x, hx, lx, n4);
        n4 = 3 * Cdim * Cdim / 4;
        split_f32<<<(n4 + 255) / 256, 256>>>((const float4*)qkv_w, hw, lw, n4);
        n4 = Cdim * Cdim / 4;
        split_f32<<<(n4 + 255) / 256, 256>>>((const float4*)proj_w, hp, lp, n4);
    }

    dim3 g1(3 * Cdim / 128, Bdim * Ldim / 128);
    tgemm_pre<true><<<g1, 256, SMEM_GEMM2>>>(nullptr, nullptr);

    rope_norm<<<Bdim * Ldim, 512>>>(rope, scale_mul);

    dim3 g3(Ldim / 128, Bdim * Hdim);
    flash_mma<<<g3, 256, SMEM_FLASH>>>();

    dim3 g2(Cdim / 128, Bdim * Ldim / 128);
    tgemm_pre<false><<<g2, 256, SMEM_GEMM2>>>(proj_b, (float*)d_out);
}